// round 11
// baseline (speedup 1.0000x reference)
#include <cuda_runtime.h>
#include <cuda_fp16.h>
#include <cstdint>

#define MDIM 8192
#define NDIM 11008
#define KDIM 4096
#define BM 128
#define BN 128
#define BK 64
#define NTHREADS 128                // 4 warps, 2x2 grid of 64x64 warp tiles
#define KTILES (KDIM / BK)          // 64
#define STAGES 3

#define LDS_W 72                    // halfs per smem row (144 B)
#define ROW_B 144
#define A_BYTES (BM * ROW_B)        // 18432
#define B_BYTES (BN * ROW_B)        // 18432
#define STAGE_BYTES (A_BYTES + B_BYTES)   // 36864
#define SMEM_TOTAL (STAGES * STAGE_BYTES) // 110592

static_assert(MDIM % BM == 0 && NDIM % BN == 0 && KDIM % BK == 0, "tiling");

// ---- scratch: fp16 x and pre-dequantized fp16 W ----
__device__ __half g_x[(size_t)MDIM * KDIM];   // 64 MB
__device__ __half g_w[(size_t)NDIM * KDIM];   // 86 MB

__device__ __forceinline__ uint32_t smem_u32(const void* p) {
    return (uint32_t)__cvta_generic_to_shared(p);
}
__device__ __forceinline__ uint32_t h2u(__half2 h) {
    return *reinterpret_cast<uint32_t*>(&h);
}
__device__ __forceinline__ void mma16816(float acc[4],
    uint32_t a0, uint32_t a1, uint32_t a2, uint32_t a3,
    uint32_t b0, uint32_t b1)
{
    asm volatile(
        "mma.sync.aligned.m16n8k16.row.col.f32.f16.f16.f32 "
        "{%0,%1,%2,%3},{%4,%5,%6,%7},{%8,%9},{%0,%1,%2,%3};"
        : "+f"(acc[0]), "+f"(acc[1]), "+f"(acc[2]), "+f"(acc[3])
        : "r"(a0), "r"(a1), "r"(a2), "r"(a3), "r"(b0), "r"(b1));
}
#define CP_ASYNC16(dst, src) \
    asm volatile("cp.async.cg.shared.global [%0], [%1], 16;" :: "r"(dst), "l"(src) : "memory")
#define CP_COMMIT() asm volatile("cp.async.commit_group;" ::: "memory")

// ---- prepass 1: x fp32 -> fp16 (lossless; values are fp16-representable) ----
__global__ void convert_x_kernel(const float* __restrict__ x) {
    size_t i = ((size_t)blockIdx.x * blockDim.x + threadIdx.x) * 4;
    if (i >= (size_t)MDIM * KDIM) return;
    float4 f = *reinterpret_cast<const float4*>(x + i);
    uint2 o;
    o.x = h2u(__floats2half2_rn(f.x, f.y));
    o.y = h2u(__floats2half2_rn(f.z, f.w));
    *reinterpret_cast<uint2*>(g_x + i) = o;
}

// ---- prepass 2: int4 packed -> fp16 dequant, (w-8)*s in fp16 (matches ref) ----
__global__ void dequant_w_kernel(const int* __restrict__ wp,
                                 const float* __restrict__ scales) {
    const size_t idx = (size_t)blockIdx.x * blockDim.x + threadIdx.x;
    if (idx >= (size_t)NDIM * 512) return;          // 512 int4-chunks per row
    const int n  = (int)(idx >> 9);
    const int kq = ((int)idx & 511) * 4;            // packed index within row
    const int grp = kq >> 6;                        // k = 2*kq, group = k/128
    const __half2 s2 = __half2half2(__float2half_rn(scales[n * 32 + grp]));
    const __half2 c1032 = __half2half2(__ushort_as_half(0x6408));   // 1032.0 exact
    int4 v4 = *reinterpret_cast<const int4*>(wp + (size_t)n * 2048 + kq);
    uint32_t v[4] = { (uint32_t)v4.x, (uint32_t)v4.y, (uint32_t)v4.z, (uint32_t)v4.w };
    uint4 o;
    uint32_t q[4];
    #pragma unroll
    for (int e = 0; e < 4; e++) {
        // one byte per int32: low nibble -> even k, high nibble -> odd k
        uint32_t t = (v[e] & 0xFu) | ((v[e] << 12) & 0x000F0000u) | 0x64006400u;
        __half2 hh = *reinterpret_cast<__half2*>(&t);
        hh = __hmul2(__hsub2(hh, c1032), s2);       // (w-8) exact, one rounding on *s
        q[e] = h2u(hh);
    }
    o.x = q[0]; o.y = q[1]; o.z = q[2]; o.w = q[3];
    *reinterpret_cast<uint4*>(g_w + (size_t)n * KDIM + kq * 2) = o;
}

// ---- main GEMM: cp.async 3-stage, 2 CTAs/SM, 4 warps of 64x64, ldmatrix ----
__global__ void __launch_bounds__(NTHREADS, 2)
w4a16_gemm_kernel(float* __restrict__ out)
{
    extern __shared__ char smem[];
    const uint32_t sb = smem_u32(smem);
    const int tid = threadIdx.x;
    const int m0 = blockIdx.x * BM;
    const int n0 = blockIdx.y * BN;

    // warp layout: 2 (M) x 2 (N), warp tile 64x64
    const int warp = tid >> 5;
    const int lane = tid & 31;
    const int wm = warp & 1;
    const int wn = warp >> 1;
    const int gid = lane >> 2;
    const int tig = lane & 3;

    // cp.async mapping: each thread owns one A row and one B row (8 x 16B chunks)
    const __half* aSrc = g_x + (size_t)(m0 + tid) * KDIM;
    const __half* bSrc = g_w + (size_t)(n0 + tid) * KDIM;

    auto issue_stage = [&](int t) {
        const int s = t % STAGES;
        const int k0 = t * BK;
        const uint32_t aDst = sb + s * STAGE_BYTES + tid * ROW_B;
        const uint32_t bDst = aDst + A_BYTES;
        #pragma unroll
        for (int j = 0; j < 8; j++) {
            CP_ASYNC16(aDst + j * 16, aSrc + k0 + j * 8);
            CP_ASYNC16(bDst + j * 16, bSrc + k0 + j * 8);
        }
        CP_COMMIT();
    };

    float acc[4][8][4];
    #pragma unroll
    for (int i = 0; i < 4; i++)
        #pragma unroll
        for (int j = 0; j < 8; j++)
            #pragma unroll
            for (int c = 0; c < 4; c++) acc[i][j][c] = 0.f;

    // ldmatrix lane->address components (choreography verified R2==R3)
    const int aRow = wm * 64 + (lane & 15);                      // + mt*16
    const int aCol = (lane >> 4) * 8;                            // + ks*16
    const int bRow = wn * 64 + (lane & 7) + ((lane >> 4) << 3);  // + p*16
    const int bCol = ((lane >> 3) & 1) * 8;                      // + ks*16

    auto compute_stage = [&](int t) {
        const int s = t % STAGES;
        const uint32_t A = sb + s * STAGE_BYTES;
        const uint32_t B = A + A_BYTES;
        #pragma unroll
        for (int ks = 0; ks < 4; ks++) {
            uint32_t a[4][4];
            #pragma unroll
            for (int mt = 0; mt < 4; mt++) {
                const uint32_t addr = A + (aRow + mt * 16) * ROW_B + (aCol + ks * 16) * 2;
                asm volatile("ldmatrix.sync.aligned.m8n8.x4.shared.b16 {%0,%1,%2,%3}, [%4];"
                    : "=r"(a[mt][0]), "=r"(a[mt][1]), "=r"(a[mt][2]), "=r"(a[mt][3])
                    : "r"(addr));
            }
            uint32_t b[8][2];
            #pragma unroll
            for (int p = 0; p < 4; p++) {
                const uint32_t addr = B + (bRow + p * 16) * ROW_B + (bCol + ks * 16) * 2;
                uint32_t r0, r1, r2, r3;
                asm volatile("ldmatrix.sync.aligned.m8n8.x4.shared.b16 {%0,%1,%2,%3}, [%4];"
                    : "=r"(r0), "=r"(r1), "=r"(r2), "=r"(r3) : "r"(addr));
                b[p * 2 + 0][0] = r0; b[p * 2 + 0][1] = r1;
                b[p * 2 + 1][0] = r2; b[p * 2 + 1][1] = r3;
            }
            #pragma unroll
            for (int mt = 0; mt < 4; mt++)
                #pragma unroll
                for (int nt = 0; nt < 8; nt++)
                    mma16816(acc[mt][nt], a[mt][0], a[mt][1], a[mt][2], a[mt][3],
                             b[nt][0], b[nt][1]);
        }
    };

    issue_stage(0);
    issue_stage(1);
    for (int t = 0; t < KTILES; t++) {
        if (t == KTILES - 1) asm volatile("cp.async.wait_group 0;" ::: "memory");
        else                 asm volatile("cp.async.wait_group 1;" ::: "memory");
        __syncthreads();
        if (t + 2 < KTILES) issue_stage(t + 2);
        compute_stage(t);
    }

    // epilogue: fp32 acc -> fp16 round (match reference cast) -> fp32 store
    float* outBase = out + (size_t)(m0 + wm * 64) * NDIM + n0 + wn * 64;
    #pragma unroll
    for (int mt = 0; mt < 4; mt++) {
        #pragma unroll
        for (int nt = 0; nt < 8; nt++) {
            float v0 = __half2float(__float2half_rn(acc[mt][nt][0]));
            float v1 = __half2float(__float2half_rn(acc[mt][nt][1]));
            float v2 = __half2float(__float2half_rn(acc[mt][nt][2]));
            float v3 = __half2float(__float2half_rn(acc[mt][nt][3]));
            *reinterpret_cast<float2*>(outBase + (size_t)(mt * 16 + gid) * NDIM + nt * 8 + tig * 2)
                = make_float2(v0, v1);
            *reinterpret_cast<float2*>(outBase + (size_t)(mt * 16 + 8 + gid) * NDIM + nt * 8 + tig * 2)
                = make_float2(v2, v3);
        }
    }
}

extern "C" void kernel_launch(void* const* d_in, const int* in_sizes, int n_in,
                              void* d_out, int out_size) {
    // Dispatch by element count (dtype-independent; fp16 refs arrive as fp32).
    const float* x      = nullptr;   // 8192*4096  fp32
    const int*   wp     = nullptr;   // 11008*2048 int32
    const float* scales = nullptr;   // 11008*32   fp32
    for (int i = 0; i < n_in; i++) {
        if      (in_sizes[i] == 33554432) x      = (const float*)d_in[i];
        else if (in_sizes[i] == 22544384) wp     = (const int*)d_in[i];
        else if (in_sizes[i] == 352256)   scales = (const float*)d_in[i];
    }
    float* out = (float*)d_out;
    if (!x || !wp || !scales) return;

    convert_x_kernel<<<(MDIM * (size_t)KDIM / 4 + 255) / 256, 256>>>(x);
    dequant_w_kernel<<<((size_t)NDIM * 512 + 255) / 256, 256>>>(wp, scales);

    cudaFuncSetAttribute(w4a16_gemm_kernel,
                         cudaFuncAttributeMaxDynamicSharedMemorySize, SMEM_TOTAL);
    dim3 grid(MDIM / BM, NDIM / BN);   // (64, 86), bm fastest for B-panel L2 reuse
    w4a16_gemm_kernel<<<grid, NTHREADS, SMEM_TOTAL>>>(out);
}

// round 12
// speedup vs baseline: 1.1962x; 1.1962x over previous
#include <cuda_runtime.h>
#include <cuda_fp16.h>
#include <cstdint>

#define MDIM 8192
#define NDIM 11008
#define KDIM 4096
#define BM 128
#define BN 128
#define BK 64
#define NTHREADS 256
#define KTILES (KDIM / BK)          // 64
#define STAGES 3

#define ROW_B 144                   // 72 halfs per smem row
#define A_BYTES (BM * ROW_B)        // 18432
#define B_BYTES (BN * ROW_B)        // 18432
#define STAGE_BYTES (A_BYTES + B_BYTES)   // 36864
#define SMEM_TOTAL (STAGES * STAGE_BYTES) // 110592

static_assert(MDIM % BM == 0 && NDIM % BN == 0 && KDIM % BK == 0, "tiling");

// ---- scratch: fp16 x and pre-dequantized fp16 W ----
__device__ __half g_x[(size_t)MDIM * KDIM];   // 64 MB
__device__ __half g_w[(size_t)NDIM * KDIM];   // 86 MB

__device__ __forceinline__ uint32_t smem_u32(const void* p) {
    return (uint32_t)__cvta_generic_to_shared(p);
}
__device__ __forceinline__ uint32_t h2u(__half2 h) {
    return *reinterpret_cast<uint32_t*>(&h);
}
__device__ __forceinline__ void mma16816(float acc[4],
    uint32_t a0, uint32_t a1, uint32_t a2, uint32_t a3,
    uint32_t b0, uint32_t b1)
{
    asm volatile(
        "mma.sync.aligned.m16n8k16.row.col.f32.f16.f16.f32 "
        "{%0,%1,%2,%3},{%4,%5,%6,%7},{%8,%9},{%0,%1,%2,%3};"
        : "+f"(acc[0]), "+f"(acc[1]), "+f"(acc[2]), "+f"(acc[3])
        : "r"(a0), "r"(a1), "r"(a2), "r"(a3), "r"(b0), "r"(b1));
}
#define CP_ASYNC16(dst, src) \
    asm volatile("cp.async.cg.shared.global [%0], [%1], 16;" :: "r"(dst), "l"(src) : "memory")
#define CP_COMMIT() asm volatile("cp.async.commit_group;" ::: "memory")
#define LDSM_X4(r0, r1, r2, r3, addr) \
    asm volatile("ldmatrix.sync.aligned.m8n8.x4.shared.b16 {%0,%1,%2,%3}, [%4];" \
        : "=r"(r0), "=r"(r1), "=r"(r2), "=r"(r3) : "r"(addr))

// ---- prepass 1: x fp32 -> fp16 (lossless; values are fp16-representable) ----
__global__ void convert_x_kernel(const float* __restrict__ x) {
    size_t i = ((size_t)blockIdx.x * blockDim.x + threadIdx.x) * 4;
    if (i >= (size_t)MDIM * KDIM) return;
    float4 f = *reinterpret_cast<const float4*>(x + i);
    uint2 o;
    o.x = h2u(__floats2half2_rn(f.x, f.y));
    o.y = h2u(__floats2half2_rn(f.z, f.w));
    *reinterpret_cast<uint2*>(g_x + i) = o;
}

// ---- prepass 2: int4 packed -> fp16 dequant, (w-8)*s in fp16 (matches ref) ----
__global__ void dequant_w_kernel(const int* __restrict__ wp,
                                 const float* __restrict__ scales) {
    const size_t idx = (size_t)blockIdx.x * blockDim.x + threadIdx.x;
    if (idx >= (size_t)NDIM * 512) return;
    const int n  = (int)(idx >> 9);
    const int kq = ((int)idx & 511) * 4;
    const int grp = kq >> 6;
    const __half2 s2 = __half2half2(__float2half_rn(scales[n * 32 + grp]));
    const __half2 c1032 = __half2half2(__ushort_as_half(0x6408));   // 1032.0 exact
    int4 v4 = *reinterpret_cast<const int4*>(wp + (size_t)n * 2048 + kq);
    uint32_t v[4] = { (uint32_t)v4.x, (uint32_t)v4.y, (uint32_t)v4.z, (uint32_t)v4.w };
    uint4 o;
    uint32_t q[4];
    #pragma unroll
    for (int e = 0; e < 4; e++) {
        uint32_t t = (v[e] & 0xFu) | ((v[e] << 12) & 0x000F0000u) | 0x64006400u;
        __half2 hh = *reinterpret_cast<__half2*>(&t);
        hh = __hmul2(__hsub2(hh, c1032), s2);       // (w-8) exact, one rounding on *s
        q[e] = h2u(hh);
    }
    o.x = q[0]; o.y = q[1]; o.z = q[2]; o.w = q[3];
    *reinterpret_cast<uint4*>(g_w + (size_t)n * KDIM + kq * 2) = o;
}

// ---- main GEMM: 3-stage cp.async, 2 CTAs/SM, 8 warps 64x32, pipelined frags ----
__global__ void __launch_bounds__(NTHREADS, 2)
w4a16_gemm_kernel(float* __restrict__ out)
{
    extern __shared__ char smem[];
    const uint32_t sb = smem_u32(smem);
    const int tid = threadIdx.x;
    const int m0 = blockIdx.x * BM;
    const int n0 = blockIdx.y * BN;

    const int warp = tid >> 5;
    const int lane = tid & 31;
    const int wm = warp & 1;        // 2 warps M
    const int wn = warp >> 1;       // 4 warps N
    const int gid = lane >> 2;
    const int tig = lane & 3;

    // cp.async mapping: thread -> row tid>>1, 4 of 8 16B-chunks per row
    const int prow = tid >> 1;
    const int pcol = (tid & 1) * 4;
    const __half* aSrc = g_x + (size_t)(m0 + prow) * KDIM + pcol * 8;
    const __half* bSrc = g_w + (size_t)(n0 + prow) * KDIM + pcol * 8;

    auto issue_stage = [&](int t) {
        const int s = t % STAGES;
        const int k0 = t * BK;
        const uint32_t aDst = sb + s * STAGE_BYTES + prow * ROW_B + pcol * 16;
        const uint32_t bDst = aDst + A_BYTES;
        #pragma unroll
        for (int j = 0; j < 4; j++) {
            CP_ASYNC16(aDst + j * 16, aSrc + k0 + j * 8);
            CP_ASYNC16(bDst + j * 16, bSrc + k0 + j * 8);
        }
        CP_COMMIT();
    };

    float acc[4][4][4];
    #pragma unroll
    for (int i = 0; i < 4; i++)
        #pragma unroll
        for (int j = 0; j < 4; j++)
            #pragma unroll
            for (int c = 0; c < 4; c++) acc[i][j][c] = 0.f;

    // ldmatrix lane->address components (choreography verified R2==R3)
    const int aRow = wm * 64 + (lane & 15);                      // + mt*16
    const int aCol = (lane >> 4) * 8;                            // + ks*16
    const int bRow = wn * 32 + (lane & 7) + ((lane >> 4) << 3);  // + p*16
    const int bCol = ((lane >> 3) & 1) * 8;                      // + ks*16

    auto compute_stage = [&](int t) {
        const int s = t % STAGES;
        const uint32_t A = sb + s * STAGE_BYTES;
        const uint32_t B = A + A_BYTES;

        uint32_t a[2][4][4];        // [buf][mt][frag]
        uint32_t b[2][4][2];        // [buf][nt][frag]

        auto load_frags = [&](int ks, int buf) {
            #pragma unroll
            for (int mt = 0; mt < 4; mt++) {
                const uint32_t addr = A + (aRow + mt * 16) * ROW_B + (aCol + ks * 16) * 2;
                LDSM_X4(a[buf][mt][0], a[buf][mt][1], a[buf][mt][2], a[buf][mt][3], addr);
            }
            #pragma unroll
            for (int p = 0; p < 2; p++) {
                const uint32_t addr = B + (bRow + p * 16) * ROW_B + (bCol + ks * 16) * 2;
                uint32_t r0, r1, r2, r3;
                LDSM_X4(r0, r1, r2, r3, addr);
                b[buf][p * 2 + 0][0] = r0; b[buf][p * 2 + 0][1] = r1;
                b[buf][p * 2 + 1][0] = r2; b[buf][p * 2 + 1][1] = r3;
            }
        };

        load_frags(0, 0);
        #pragma unroll
        for (int ks = 0; ks < 4; ks++) {
            const int cur = ks & 1;
            if (ks < 3) load_frags(ks + 1, cur ^ 1);   // prefetch: no dep on MMAs below
            #pragma unroll
            for (int mt = 0; mt < 4; mt++)
                #pragma unroll
                for (int nt = 0; nt < 4; nt++)
                    mma16816(acc[mt][nt],
                             a[cur][mt][0], a[cur][mt][1], a[cur][mt][2], a[cur][mt][3],
                             b[cur][nt][0], b[cur][nt][1]);
        }
    };

    issue_stage(0);
    issue_stage(1);
    for (int t = 0; t < KTILES; t++) {
        if (t == KTILES - 1) asm volatile("cp.async.wait_group 0;" ::: "memory");
        else                 asm volatile("cp.async.wait_group 1;" ::: "memory");
        __syncthreads();
        if (t + 2 < KTILES) issue_stage(t + 2);
        compute_stage(t);
    }

    // epilogue: fp32 acc -> fp16 round (match reference cast) -> fp32 store
    float* outBase = out + (size_t)(m0 + wm * 64) * NDIM + n0 + wn * 32;
    #pragma unroll
    for (int mt = 0; mt < 4; mt++) {
        #pragma unroll
        for (int nt = 0; nt < 4; nt++) {
            float v0 = __half2float(__float2half_rn(acc[mt][nt][0]));
            float v1 = __half2float(__float2half_rn(acc[mt][nt][1]));
            float v2 = __half2float(__float2half_rn(acc[mt][nt][2]));
            float v3 = __half2float(__float2half_rn(acc[mt][nt][3]));
            *reinterpret_cast<float2*>(outBase + (size_t)(mt * 16 + gid) * NDIM + nt * 8 + tig * 2)
                = make_float2(v0, v1);
            *reinterpret_cast<float2*>(outBase + (size_t)(mt * 16 + 8 + gid) * NDIM + nt * 8 + tig * 2)
                = make_float2(v2, v3);
        }
    }
}

extern "C" void kernel_launch(void* const* d_in, const int* in_sizes, int n_in,
                              void* d_out, int out_size) {
    // Dispatch by element count (dtype-independent; fp16 refs arrive as fp32).
    const float* x      = nullptr;   // 8192*4096  fp32
    const int*   wp     = nullptr;   // 11008*2048 int32
    const float* scales = nullptr;   // 11008*32   fp32
    for (int i = 0; i < n_in; i++) {
        if      (in_sizes[i] == 33554432) x      = (const float*)d_in[i];
        else if (in_sizes[i] == 22544384) wp     = (const int*)d_in[i];
        else if (in_sizes[i] == 352256)   scales = (const float*)d_in[i];
    }
    float* out = (float*)d_out;
    if (!x || !wp || !scales) return;

    convert_x_kernel<<<(MDIM * (size_t)KDIM / 4 + 255) / 256, 256>>>(x);
    dequant_w_kernel<<<((size_t)NDIM * 512 + 255) / 256, 256>>>(wp, scales);

    cudaFuncSetAttribute(w4a16_gemm_kernel,
                         cudaFuncAttributeMaxDynamicSharedMemorySize, SMEM_TOTAL);
    dim3 grid(MDIM / BM, NDIM / BN);   // (64, 86), bm fastest for B-panel L2 reuse
    w4a16_gemm_kernel<<<grid, NTHREADS, SMEM_TOTAL>>>(out);
}

// round 15
// speedup vs baseline: 1.9194x; 1.6045x over previous
#include <cuda_runtime.h>
#include <cuda_fp16.h>
#include <cstdint>

#define MDIM 8192
#define NDIM 11008
#define KDIM 4096
#define KT   (KDIM / 64)        // 64 k-tiles of 64
#define NTHREADS 128            // 4 warps: 2(M) x 2(N) of 64x64 warp tiles

// ---- fragment-packed scratch ----
// A chunks (16B): idx = ((((bm*64+kt)*2+wm)*4+ks)*4+mt)*32 + lane
//   chunk = {x[m][kb,kb+1], x[m+8][kb,kb+1], x[m][kb+8,kb+9], x[m+8][kb+8,kb+9]}
//   m = bm*128 + wm*64 + mt*16 + (lane>>2), kb = kt*64 + ks*16 + (lane&3)*2
// B chunks (16B): idx = ((((bn*64+kt)*2+wn)*4+ks)*4+p)*32 + lane
//   chunk = {W[n1][kb],W[n1][kb+1], W[n1][kb+8],W[n1][kb+9],
//            W[n2][kb],...,          W[n2][kb+8],...}   (two half2 per n)
//   n1 = bn*128 + wn*64 + (2p)*8 + gid, n2 = ... + (2p+1)*8 + gid
__device__ uint4 g_xa[(size_t)MDIM * KDIM / 8];   // 64 MB
__device__ uint4 g_wb[(size_t)NDIM * KDIM / 8];   // 86 MB

__device__ __forceinline__ uint32_t h2u(__half2 h) {
    return *reinterpret_cast<uint32_t*>(&h);
}
__device__ __forceinline__ void mma16816(float acc[4],
    uint32_t a0, uint32_t a1, uint32_t a2, uint32_t a3,
    uint32_t b0, uint32_t b1)
{
    asm volatile(
        "mma.sync.aligned.m16n8k16.row.col.f32.f16.f16.f32 "
        "{%0,%1,%2,%3},{%4,%5,%6,%7},{%8,%9},{%0,%1,%2,%3};"
        : "+f"(acc[0]), "+f"(acc[1]), "+f"(acc[2]), "+f"(acc[3])
        : "r"(a0), "r"(a1), "r"(a2), "r"(a3), "r"(b0), "r"(b1));
}

// ---- prepass 1: pack x (fp32 carrying fp16 values) into A-fragment chunks ----
__global__ void pack_a_kernel(const float* __restrict__ x) {
    const size_t c = (size_t)blockIdx.x * blockDim.x + threadIdx.x;
    if (c >= (size_t)MDIM * KDIM / 8) return;
    const int lane = (int)(c & 31);
    const int mt   = (int)(c >> 5) & 3;
    const int ks   = (int)(c >> 7) & 3;
    const int wm   = (int)(c >> 9) & 1;
    const int kt   = (int)(c >> 10) & 63;
    const int bm   = (int)(c >> 16);
    const int gid = lane >> 2, tig = lane & 3;
    const int m  = bm * 128 + wm * 64 + mt * 16 + gid;
    const int kb = kt * 64 + ks * 16 + tig * 2;
    const float* p0 = x + (size_t)m * KDIM + kb;
    const float* p1 = x + (size_t)(m + 8) * KDIM + kb;
    float2 f0 = *reinterpret_cast<const float2*>(p0);       // a0
    float2 f1 = *reinterpret_cast<const float2*>(p1);       // a1
    float2 f2 = *reinterpret_cast<const float2*>(p0 + 8);   // a2
    float2 f3 = *reinterpret_cast<const float2*>(p1 + 8);   // a3
    uint4 o;
    o.x = h2u(__floats2half2_rn(f0.x, f0.y));
    o.y = h2u(__floats2half2_rn(f1.x, f1.y));
    o.z = h2u(__floats2half2_rn(f2.x, f2.y));
    o.w = h2u(__floats2half2_rn(f3.x, f3.y));
    g_xa[c] = o;
}

// ---- prepass 2: dequantize int4 W and pack into B-fragment chunks ----
__device__ __forceinline__ uint32_t dq2(uint32_t v, __half2 s2) {
    const __half2 c1032 = __half2half2(__ushort_as_half(0x6408));   // 1032.0 exact
    uint32_t t = (v & 0xFu) | ((v << 12) & 0x000F0000u) | 0x64006400u;
    __half2 hh = *reinterpret_cast<__half2*>(&t);
    hh = __hmul2(__hsub2(hh, c1032), s2);       // (w-8) exact, one rounding on *s
    return h2u(hh);
}
__global__ void pack_b_kernel(const int* __restrict__ wp,
                              const float* __restrict__ scales) {
    const size_t c = (size_t)blockIdx.x * blockDim.x + threadIdx.x;
    if (c >= (size_t)NDIM * KDIM / 8) return;
    const int lane = (int)(c & 31);
    const int p    = (int)(c >> 5) & 3;
    const int ks   = (int)(c >> 7) & 3;
    const int wn   = (int)(c >> 9) & 1;
    const int kt   = (int)(c >> 10) & 63;
    const int bn   = (int)(c >> 16);
    const int gid = lane >> 2, tig = lane & 3;
    const int n1 = bn * 128 + wn * 64 + (2 * p) * 8 + gid;
    const int n2 = n1 + 8;
    const int kq = ks * 8 + tig;            // packed int32 index for kb (within ktile)
    const int kqg = kt * 32 + kq;           // global packed index (K/2 = 2048 per row)
    const int grp = kt >> 1;                // scale group = k/128
    const __half2 s1 = __half2half2(__float2half_rn(scales[n1 * 32 + grp]));
    const __half2 s2 = __half2half2(__float2half_rn(scales[n2 * 32 + grp]));
    const uint32_t t1 = (uint32_t)wp[(size_t)n1 * 2048 + kqg];
    const uint32_t t2 = (uint32_t)wp[(size_t)n1 * 2048 + kqg + 4];   // kb+8
    const uint32_t t3 = (uint32_t)wp[(size_t)n2 * 2048 + kqg];
    const uint32_t t4 = (uint32_t)wp[(size_t)n2 * 2048 + kqg + 4];
    uint4 o;
    o.x = dq2(t1, s1);   // n1: kb, kb+1
    o.y = dq2(t2, s1);   // n1: kb+8, kb+9
    o.z = dq2(t3, s2);   // n2: kb, kb+1
    o.w = dq2(t4, s2);   // n2: kb+8, kb+9
    g_wb[c] = o;
}

// ---- main GEMM: no smem, no syncs; pure LDG fragment streaming + mma.sync ----
__global__ void __launch_bounds__(NTHREADS, 2)
w4a16_gemm_kernel(float* __restrict__ out)
{
    const int tid = threadIdx.x;
    const int warp = tid >> 5;
    const int lane = tid & 31;
    const int wm = warp & 1;
    const int wn = warp >> 1;
    const int gid = lane >> 2;
    const int tig = lane & 3;
    const int bm = blockIdx.x;
    const int bn = blockIdx.y;

    // chunk-unit bases (uint4): per (kt): A block 1024 chunks, same for B
    const uint4* aBase = g_xa + ((size_t)bm * 64 * 2 + wm) * 2048 / 4 + lane;
    const uint4* bBase = g_wb + ((size_t)bn * 64 * 2 + wn) * 2048 / 4 + lane;
    // layout strides: kt*1024, ks*128, (mt|p)*32   [wm/wn stride = 512]

    float acc[4][8][4];
    #pragma unroll
    for (int i = 0; i < 4; i++)
        #pragma unroll
        for (int j = 0; j < 8; j++)
            #pragma unroll
            for (int q = 0; q < 4; q++) acc[i][j][q] = 0.f;

    uint4 af[2][4];
    uint4 bf[2][4];

    auto ld_step = [&](int kt, int ks, int buf) {
        const uint4* ap = aBase + kt * 1024 + ks * 128;
        const uint4* bp = bBase + kt * 1024 + ks * 128;
        #pragma unroll
        for (int mt = 0; mt < 4; mt++) af[buf][mt] = __ldg(ap + mt * 32);
        #pragma unroll
        for (int p = 0; p < 4; p++)    bf[buf][p]  = __ldg(bp + p * 32);
    };

    ld_step(0, 0, 0);
    for (int kt = 0; kt < KT; kt++) {
        #pragma unroll
        for (int ks = 0; ks < 4; ks++) {
            const int cur = ks & 1;
            const int u = kt * 4 + ks + 1;          // next step
            if (u < KT * 4) ld_step(u >> 2, u & 3, cur ^ 1);
            #pragma unroll
            for (int mt = 0; mt < 4; mt++) {
                const uint4 a = af[cur][mt];
                #pragma unroll
                for (int p = 0; p < 4; p++) {
                    const uint4 b = bf[cur][p];
                    mma16816(acc[mt][2 * p],     a.x, a.y, a.z, a.w, b.x, b.y);
                    mma16816(acc[mt][2 * p + 1], a.x, a.y, a.z, a.w, b.z, b.w);
                }
            }
        }
    }

    // epilogue: fp32 acc -> fp16 round (match reference cast) -> fp32 store
    float* outBase = out + (size_t)(bm * 128 + wm * 64) * NDIM + bn * 128 + wn * 64;
    #pragma unroll
    for (int mt = 0; mt < 4; mt++) {
        #pragma unroll
        for (int nt = 0; nt < 8; nt++) {
            float v0 = __half2float(__float2half_rn(acc[mt][nt][0]));
            float v1 = __half2float(__float2half_rn(acc[mt][nt][1]));
            float v2 = __half2float(__float2half_rn(acc[mt][nt][2]));
            float v3 = __half2float(__float2half_rn(acc[mt][nt][3]));
            *reinterpret_cast<float2*>(outBase + (size_t)(mt * 16 + gid) * NDIM + nt * 8 + tig * 2)
                = make_float2(v0, v1);
            *reinterpret_cast<float2*>(outBase + (size_t)(mt * 16 + 8 + gid) * NDIM + nt * 8 + tig * 2)
                = make_float2(v2, v3);
        }
    }
}

extern "C" void kernel_launch(void* const* d_in, const int* in_sizes, int n_in,
                              void* d_out, int out_size) {
    // Dispatch by element count (dtype-independent; fp16 refs arrive as fp32).
    const float* x      = nullptr;   // 8192*4096  fp32
    const int*   wp     = nullptr;   // 11008*2048 int32
    const float* scales = nullptr;   // 11008*32   fp32
    for (int i = 0; i < n_in; i++) {
        if      (in_sizes[i] == 33554432) x      = (const float*)d_in[i];
        else if (in_sizes[i] == 22544384) wp     = (const int*)d_in[i];
        else if (in_sizes[i] == 352256)   scales = (const float*)d_in[i];
    }
    float* out = (float*)d_out;
    if (!x || !wp || !scales) return;

    const size_t aChunks = (size_t)MDIM * KDIM / 8;   // 4,194,304
    const size_t bChunks = (size_t)NDIM * KDIM / 8;   // 5,636,096
    pack_a_kernel<<<(unsigned)((aChunks + 255) / 256), 256>>>(x);
    pack_b_kernel<<<(unsigned)((bChunks + 255) / 256), 256>>>(wp, scales);

    dim3 grid(MDIM / 128, NDIM / 128);    // (64, 86)
    w4a16_gemm_kernel<<<grid, NTHREADS>>>(out);
}